// round 15
// baseline (speedup 1.0000x reference)
#include <cuda_runtime.h>

#define NHEADS 4
typedef unsigned long long u64;

// Scratch (allocation-free). Zero at module load; epilogue re-zeroes after
// reading so every graph replay observes zeros (deterministic).
__device__ float g_S[NHEADS][64];          // sum_n w[h,n] * u_n
__device__ float g_z[NHEADS];              // sum_n w[h,n]
__device__ unsigned int g_ctr;             // last-block-done counter

__device__ __forceinline__ float tanh_fast(float x) {
    float y; asm("tanh.approx.f32 %0, %1;" : "=f"(y) : "f"(x)); return y;
}
__device__ __forceinline__ float exp2_fast(float x) {
    float y; asm("ex2.approx.f32 %0, %1;" : "=f"(y) : "f"(x)); return y;
}
// ---- packed f32x2 helpers ----
__device__ __forceinline__ u64 pack2(float lo, float hi) {
    u64 r; asm("mov.b64 %0, {%1, %2};" : "=l"(r) : "f"(lo), "f"(hi)); return r;
}
__device__ __forceinline__ void unpack2(u64 v, float& lo, float& hi) {
    asm("mov.b64 {%0, %1}, %2;" : "=f"(lo), "=f"(hi) : "l"(v));
}
__device__ __forceinline__ u64 fma2(u64 a, u64 b, u64 c) {
    u64 d; asm("fma.rn.f32x2 %0, %1, %2, %3;" : "=l"(d) : "l"(a), "l"(b), "l"(c)); return d;
}
__device__ __forceinline__ u64 mul2(u64 a, u64 b) {
    u64 d; asm("mul.rn.f32x2 %0, %1, %2;" : "=l"(d) : "l"(a), "l"(b)); return d;
}
__device__ __forceinline__ u64 add2(u64 a, u64 b) {
    u64 d; asm("add.rn.f32x2 %0, %1, %2;" : "=l"(d) : "l"(a), "l"(b)); return d;
}
// Predicated L2 prefetch (no BSSY, no dest register, no faulting branch).
__device__ __forceinline__ void prefetch_l2_if(const void* p, int a, int b) {
    asm volatile("{ .reg .pred pp; setp.lt.s32 pp, %1, %2; @pp prefetch.global.L2 [%0]; }"
                 :: "l"(p), "r"(a), "r"(b));
}

// ---------------------------------------------------------------------------
// Single fused kernel (R14 + distance-2 L2 prefetch).
// Main loop: warp cooperates; lane l owns hidden dims j0=l, j1=l+32.
//   16 points/iteration as two independent 8-pt halves (A, B). The two
//   score butterflies are PACKED into one f32x2 chain: pAB[i] carries
//   (chainA value i, chainB value i); lane-bit SEL / shfl_xor / add act
//   componentwise, so one packed butterfly == both scalar ones exactly.
//   Fused m=16 stage by input selection (scores linear in u). Weights
//   broadcast via smem LDS.128 (parity buffered); accumulation f32x2.
//   NEW: prefetch.global.L2 two groups ahead -> the leading LDGs hit L2
//   (~250 cyc) instead of DRAM (~600), shrinking the per-group stall.
// Epilogue: last finished block computes hbar/pooled/out, re-zeroes scratch.
//   (Race fix retained: all-thread fence + __syncthreads BEFORE counting.)
// ---------------------------------------------------------------------------
__global__ void __launch_bounds__(256, 2)
main_kernel(const float* __restrict__ rr,
            const float* __restrict__ ri,
            const float* __restrict__ W1,
            const float* __restrict__ b1,
            const float* __restrict__ W2,
            const float* __restrict__ query,
            const float* __restrict__ ipw,
            const float* __restrict__ ipb,
            const float* __restrict__ b2,
            const float* __restrict__ opw,
            const float* __restrict__ opb,
            float* __restrict__ out,
            int N) {
    __shared__ float qsh[64];
    __shared__ float ash[NHEADS][64];     // reused as hbar in epilogue
    __shared__ float atil[NHEADS][64];
    __shared__ float wb[8][2][64];        // per-warp parity-buffered weights
    __shared__ float invz[NHEADS];
    __shared__ bool  isLast;

    const int t    = threadIdx.x;
    const int lane = t & 31;
    const int wid  = t >> 5;

    // ---- prologue: q = query @ Wq^T + bq (4 threads per output) ----
    {
        int o = t >> 2, part = t & 3;
        float s = 0.f;
        const float* row = ipw + o * 64 + part * 16;
        const float* qp  = query + part * 16;
        #pragma unroll
        for (int i = 0; i < 16; ++i) s = fmaf(qp[i], row[i], s);
        s += __shfl_xor_sync(0xffffffffu, s, 1);
        s += __shfl_xor_sync(0xffffffffu, s, 2);
        if (part == 0) qsh[o] = s + ipb[o];
    }
    __syncthreads();
    // ---- a_h[c] = sum_d q[16h+d] * Wk[16h+d, c]  (Wk = ipw rows [64,128)) ----
    {
        int h = t >> 6, c = t & 63;
        float a = 0.f;
        #pragma unroll 4
        for (int d = 0; d < 16; ++d)
            a = fmaf(qsh[16 * h + d], ipw[(64 + 16 * h + d) * 64 + c], a);
        ash[h][c] = a;
    }
    __syncthreads();
    // ---- atil_h[c] = (0.25*log2e) * sum_m a_h[m] * W2[m,c] ----
    {
        const float SC = 0.25f * 1.4426950408889634f;  // scale * log2(e)
        int h = t >> 6, c = t & 63;
        float s = 0.f;
        #pragma unroll 8
        for (int m = 0; m < 64; ++m) s = fmaf(ash[h][m], W2[m * 64 + c], s);
        atil[h][c] = s * SC;
    }
    __syncthreads();

    // ---- per-lane constants (SiLU's 0.5 folded into W1/b1) ----
    const int j0 = lane, j1 = lane + 32;
    const float ka0 = 0.5f * W1[2 * j0], kb0 = 0.5f * W1[2 * j0 + 1], kc0 = 0.5f * b1[j0];
    const float ka1 = 0.5f * W1[2 * j1], kb1 = 0.5f * W1[2 * j1 + 1], kc1 = 0.5f * b1[j1];
    // Dup-packed score vectors (for the packed dual-chain score-gen).
    u64 P_A0[NHEADS], P_A1[NHEADS];
    #pragma unroll
    for (int h = 0; h < NHEADS; ++h) {
        P_A0[h] = pack2(atil[h][j0], atil[h][j0]);
        P_A1[h] = pack2(atil[h][j1], atil[h][j1]);
    }

    // Packed accumulators: (head pair) x (dim j0/j1)
    u64 acc0_01 = 0, acc0_23 = 0, acc1_01 = 0, acc1_23 = 0;
    float zloc = 0.f;   // lane-local sum of this lane's own em values

    const int gwarp  = (blockIdx.x * blockDim.x + t) >> 5;
    const int nwarps = (gridDim.x * blockDim.x) >> 5;
    const int M = N >> 4;                       // 16-pt super-groups
    const int chunk = (M + nwarps - 1) / nwarps;
    const int ms = gwarp * chunk;
    const int me = min(M, ms + chunk);

    const float4* rr4 = (const float4*)rr + 4 * ms;
    const float4* ri4 = (const float4*)ri + 4 * ms;
    const bool hi16 = (lane & 16) != 0;

    for (int m = ms; m < me; ++m, rr4 += 4, ri4 += 4) {
        // ---- all 16 points' loads issue back-to-back (one latency wait) ----
        float4 rA0 = __ldg(rr4),     rA1 = __ldg(rr4 + 1);
        float4 rB0 = __ldg(rr4 + 2), rB1 = __ldg(rr4 + 3);
        float4 iA0 = __ldg(ri4),     iA1 = __ldg(ri4 + 1);
        float4 iB0 = __ldg(ri4 + 2), iB1 = __ldg(ri4 + 3);
        // ---- L2 prefetch two groups ahead (bounded, predicated) ----
        prefetch_l2_if(rr4 + 8, m + 2, me);
        prefetch_l2_if(ri4 + 8, m + 2, me);

        // ---- half A: MLP + SiLU ----
        float reA[8] = {rA0.x, rA0.y, rA0.z, rA0.w, rA1.x, rA1.y, rA1.z, rA1.w};
        float imA[8] = {iA0.x, iA0.y, iA0.z, iA0.w, iA1.x, iA1.y, iA1.z, iA1.w};
        float u0A[8], u1A[8];
        #pragma unroll
        for (int pt = 0; pt < 8; ++pt) {
            float h0 = fmaf(ka0, reA[pt], fmaf(kb0, imA[pt], kc0));
            float h1 = fmaf(ka1, reA[pt], fmaf(kb1, imA[pt], kc1));
            u0A[pt] = fmaf(h0, tanh_fast(h0), h0);
            u1A[pt] = fmaf(h1, tanh_fast(h1), h1);
        }
        // ---- half B: MLP + SiLU (independent; fills half-A stall slots) ----
        float reB[8] = {rB0.x, rB0.y, rB0.z, rB0.w, rB1.x, rB1.y, rB1.z, rB1.w};
        float imB[8] = {iB0.x, iB0.y, iB0.z, iB0.w, iB1.x, iB1.y, iB1.z, iB1.w};
        float u0B[8], u1B[8];
        #pragma unroll
        for (int pt = 0; pt < 8; ++pt) {
            float h0 = fmaf(ka0, reB[pt], fmaf(kb0, imB[pt], kc0));
            float h1 = fmaf(ka1, reB[pt], fmaf(kb1, imB[pt], kc1));
            u0B[pt] = fmaf(h0, tanh_fast(h0), h0);
            u1B[pt] = fmaf(h1, tanh_fast(h1), h1);
        }

        // ---- packed score gen with fused m=16 stage ----
        // Input selection per half (scores are linear in u), then pack the
        // selected scalars so each u64 carries (chainA, chainB). pAB[i]
        // holds value index i for BOTH chains.
        u64 pAB[16];
        #pragma unroll
        for (int pt = 0; pt < 4; ++pt) {
            float a0A = hi16 ? u0A[pt + 4] : u0A[pt];
            float a1A = hi16 ? u1A[pt + 4] : u1A[pt];
            float b0A = hi16 ? u0A[pt]     : u0A[pt + 4];
            float b1A = hi16 ? u1A[pt]     : u1A[pt + 4];
            float a0B = hi16 ? u0B[pt + 4] : u0B[pt];
            float a1B = hi16 ? u1B[pt + 4] : u1B[pt];
            float b0B = hi16 ? u0B[pt]     : u0B[pt + 4];
            float b1B = hi16 ? u1B[pt]     : u1B[pt + 4];
            u64 aw0 = pack2(a0A, a0B), aw1 = pack2(a1A, a1B);
            u64 bw0 = pack2(b0A, b0B), bw1 = pack2(b1A, b1B);
            #pragma unroll
            for (int h = 0; h < NHEADS; ++h) {
                u64 kp = fma2(P_A0[h], aw0, mul2(P_A1[h], aw1));  // own half
                u64 sp = fma2(P_A0[h], bw0, mul2(P_A1[h], bw1));  // partner's
                pAB[pt * 4 + h] = add2(kp, __shfl_xor_sync(0xffffffffu, sp, 16));
            }
        }
        // ---- packed butterfly, stages m=8..1 (both chains at once) ----
        #pragma unroll
        for (int s = 8; s >= 1; s >>= 1) {
            const bool hi = (lane & s) != 0;
            #pragma unroll
            for (int i = 0; i < s; ++i) {
                u64 keep = hi ? pAB[i + s] : pAB[i];
                u64 send = hi ? pAB[i] : pAB[i + s];
                pAB[i] = add2(keep, __shfl_xor_sync(0xffffffffu, send, s));
            }
        }
        float sA, sB; unpack2(pAB[0], sA, sB);
        float emA = exp2_fast(sA);      // exp(score(ptA=lane>>2, h=lane&3))
        float emB = exp2_fast(sB);      // exp(score(ptB=lane>>2, h=lane&3))
        zloc += emA + emB;
        // ---- broadcast 64 weights via smem (parity double-buffered) ----
        float* wrow = &wb[wid][m & 1][0];
        wrow[lane] = emA; wrow[lane + 32] = emB;
        __syncwarp();
        // Weights read as ulonglong2: (w0,w1),(w2,w3) arrive as f32x2-ready
        // register pairs straight from LDS.128 -> zero pack MOVs.
        const ulonglong2* wp2 = (const ulonglong2*)wrow;
        #pragma unroll
        for (int pt = 0; pt < 8; ++pt) {
            ulonglong2 W = wp2[pt];                  // half A weights, pt
            u64 D0 = pack2(u0A[pt], u0A[pt]), D1 = pack2(u1A[pt], u1A[pt]);
            acc0_01 = fma2(W.x, D0, acc0_01);
            acc0_23 = fma2(W.y, D0, acc0_23);
            acc1_01 = fma2(W.x, D1, acc1_01);
            acc1_23 = fma2(W.y, D1, acc1_23);
        }
        #pragma unroll
        for (int pt = 0; pt < 8; ++pt) {
            ulonglong2 W = wp2[pt + 8];              // half B weights, pt
            u64 D0 = pack2(u0B[pt], u0B[pt]), D1 = pack2(u1B[pt], u1B[pt]);
            acc0_01 = fma2(W.x, D0, acc0_01);
            acc0_23 = fma2(W.y, D0, acc0_23);
            acc1_01 = fma2(W.x, D1, acc1_01);
            acc1_23 = fma2(W.y, D1, acc1_23);
        }
    }

    float acc0[NHEADS], acc1[NHEADS];
    unpack2(acc0_01, acc0[0], acc0[1]); unpack2(acc0_23, acc0[2], acc0[3]);
    unpack2(acc1_01, acc1[0], acc1[1]); unpack2(acc1_23, acc1[2], acc1[3]);

    // Tail points (N % 16): warp 0 only, scalar butterfly path (atil via smem).
    float ztl[NHEADS] = {0.f, 0.f, 0.f, 0.f};
    if (gwarp == 0) {
        for (int n = (M << 4); n < N; ++n) {
            float re = rr[n], im = ri[n];
            float h0 = fmaf(ka0, re, fmaf(kb0, im, kc0));
            float h1 = fmaf(ka1, re, fmaf(kb1, im, kc1));
            float v0 = fmaf(h0, tanh_fast(h0), h0);
            float v1 = fmaf(h1, tanh_fast(h1), h1);
            #pragma unroll
            for (int h = 0; h < NHEADS; ++h) {
                float s = fmaf(atil[h][j0], v0, atil[h][j1] * v1);
                #pragma unroll
                for (int mm = 16; mm >= 1; mm >>= 1)
                    s += __shfl_xor_sync(0xffffffffu, s, mm);
                float w = exp2_fast(s);
                ztl[h] += w;
                acc0[h] = fmaf(w, v0, acc0[h]);
                acc1[h] = fmaf(w, v1, acc1[h]);
            }
        }
    }

    // Commit warp partials (lane-distinct addresses; no intra-warp contention)
    #pragma unroll
    for (int h = 0; h < NHEADS; ++h) {
        atomicAdd(&g_S[h][j0], acc0[h]);
        atomicAdd(&g_S[h][j1], acc1[h]);
    }
    // zloc at lane l belongs to head h=l&3; same-h lanes differ in bits {2,3,4}
    float zs = zloc + __shfl_xor_sync(0xffffffffu, zloc, 16);
    zs += __shfl_xor_sync(0xffffffffu, zs, 8);
    zs += __shfl_xor_sync(0xffffffffu, zs, 4);
    if (lane < NHEADS) atomicAdd(&g_z[lane], zs);
    if (gwarp == 0 && lane == 0) {
        #pragma unroll
        for (int h = 0; h < NHEADS; ++h) atomicAdd(&g_z[h], ztl[h]);
    }

    // ---- epilogue: last block computes the output -------------------------
    // RACE FIX: every thread fences its own atomics; the block barrier then
    // guarantees ALL warps of this block have fenced before thread 0 counts
    // the block as done.
    __threadfence();
    __syncthreads();
    if (t == 0) {
        unsigned v = atomicAdd(&g_ctr, 1u);
        isLast = (v == gridDim.x - 1);
        if (isLast) g_ctr = 0;           // all blocks incremented; safe reset
    }
    __syncthreads();
    if (!isLast) return;

    float* hbar = &ash[0][0];            // reuse [4][64]
    float* pooled = qsh;                 // reuse [64]
    if (t < NHEADS) invz[t] = __frcp_rn(__ldcg(&g_z[t]));
    __syncthreads();
    {
        int h = t >> 6, j = t & 63;
        float s = 0.f;
        #pragma unroll 8
        for (int mm = 0; mm < 64; ++mm)
            s = fmaf(W2[j * 64 + mm], __ldcg(&g_S[h][mm]), s);
        hbar[h * 64 + j] = fmaf(s, invz[h], b2[j]);
    }
    __syncthreads();
    // scratch reset for next graph replay (all reads of g_S/g_z done)
    ((float*)g_S)[t] = 0.f;
    if (t < NHEADS) g_z[t] = 0.f;
    if (t < 64) {
        int h = t >> 4;
        float s = ipb[128 + t];          // Wv row (128+t) dot hbar_h + bv
        #pragma unroll 8
        for (int mm = 0; mm < 64; ++mm)
            s = fmaf(ipw[(128 + t) * 64 + mm], hbar[h * 64 + mm], s);
        pooled[t] = s;
    }
    __syncthreads();
    if (t < 64) {
        float s = opb[t];
        #pragma unroll 8
        for (int k = 0; k < 64; ++k) s = fmaf(opw[t * 64 + k], pooled[k], s);
        out[t] = s;
    }
}

// ---------------------------------------------------------------------------
extern "C" void kernel_launch(void* const* d_in, const int* in_sizes, int n_in,
                              void* d_out, int out_size) {
    // Inputs (metadata order): rho_real, rho_imag, l_A, l_B, [Z_A, Z_B,]
    // W1, b1, W2, b2, query, in_proj_w, in_proj_b, out_proj_w, out_proj_b.
    const float* rr    = (const float*)d_in[0];
    const float* ri    = (const float*)d_in[1];
    const float* W1    = (const float*)d_in[n_in - 9];
    const float* b1    = (const float*)d_in[n_in - 8];
    const float* W2    = (const float*)d_in[n_in - 7];
    const float* b2    = (const float*)d_in[n_in - 6];
    const float* query = (const float*)d_in[n_in - 5];
    const float* ipw   = (const float*)d_in[n_in - 4];
    const float* ipb   = (const float*)d_in[n_in - 3];
    const float* opw   = (const float*)d_in[n_in - 2];
    const float* opb   = (const float*)d_in[n_in - 1];
    int N = in_sizes[0];

    main_kernel<<<296, 256>>>(rr, ri, W1, b1, W2, query, ipw, ipb,
                              b2, opw, opb, (float*)d_out, N);
}